// round 1
// baseline (speedup 1.0000x reference)
#include <cuda_runtime.h>
#include <math.h>

// Problem constants
#define NN      100000
#define EE      1600000
#define INDIM   128
#define HIDD    64
#define NHEADS  4
#define ODIM    64

// ---------------------------------------------------------------------------
// Scratch (device globals — the sanctioned no-alloc path)
// ---------------------------------------------------------------------------
__device__ float g_bufA[(size_t)NN * 256];   // GEMM outputs (h)
__device__ float g_bufB[(size_t)NN * 256];   // aggregated/ELU outputs
__device__ float g_alphaS[NN * NHEADS];
__device__ float g_alphaD[NN * NHEADS];
__device__ int   g_rowptr[NN + 1];
__device__ int   g_fill[NN];
__device__ int   g_csr_src[EE];
__device__ int   g_bsums[128];

__device__ __forceinline__ float* buf_ptr(int sel) {
    return sel == 0 ? g_bufA : g_bufB;
}

// ---------------------------------------------------------------------------
// CSR build: histogram -> exclusive scan -> scatter
// ---------------------------------------------------------------------------
__global__ void k_zero_fill() {
    int i = blockIdx.x * blockDim.x + threadIdx.x;
    if (i < NN) g_fill[i] = 0;
}

__global__ void k_hist(const int* __restrict__ ei) {
    int e = blockIdx.x * blockDim.x + threadIdx.x;
    if (e < EE) atomicAdd(&g_fill[ei[EE + e]], 1);
}

// block-level scan over 1024 elements
__global__ void k_scan1() {
    __shared__ int s[1024];
    int t = threadIdx.x;
    int i = blockIdx.x * 1024 + t;
    int v = (i < NN) ? g_fill[i] : 0;
    s[t] = v;
    __syncthreads();
    #pragma unroll
    for (int off = 1; off < 1024; off <<= 1) {
        int add = (t >= off) ? s[t - off] : 0;
        __syncthreads();
        s[t] += add;
        __syncthreads();
    }
    if (i < NN) g_rowptr[i] = s[t] - v;   // exclusive
    if (t == 1023) g_bsums[blockIdx.x] = s[1023];
}

__global__ void k_scan2(int nb) {
    if (threadIdx.x == 0 && blockIdx.x == 0) {
        int run = 0;
        for (int b = 0; b < nb; b++) { int v = g_bsums[b]; g_bsums[b] = run; run += v; }
        g_rowptr[NN] = run;   // == EE
    }
}

__global__ void k_scan3() {
    int i = blockIdx.x * 1024 + threadIdx.x;
    if (i < NN) g_rowptr[i] += g_bsums[blockIdx.x];
}

__global__ void k_scatter(const int* __restrict__ ei) {
    int e = blockIdx.x * blockDim.x + threadIdx.x;
    if (e < EE) {
        int d   = ei[EE + e];
        int pos = g_rowptr[d] + atomicAdd(&g_fill[d], 1);
        g_csr_src[pos] = ei[e];
    }
}

// ---------------------------------------------------------------------------
// fp32 tiled GEMM: C[M x Ncols] = A[M x K] * B[K x Ncols], row-major.
// BM=BN=64, BK=16, 256 threads, 4x4 per thread. Only M needs guards.
// ---------------------------------------------------------------------------
__global__ void k_gemm64(const float* __restrict__ Aext, int selA, int selC,
                         const float* __restrict__ B, int M, int Ncols, int K)
{
    const float* A = Aext ? Aext : buf_ptr(selA);
    float* C = buf_ptr(selC);

    __shared__ float As[16][68];   // padded, [k][m]
    __shared__ float Bs[16][68];   // [k][n]

    int tid = threadIdx.x;
    int tx = tid & 15;    // n sub-tile
    int ty = tid >> 4;    // m sub-tile
    int rowBase = blockIdx.y * 64;
    int colBase = blockIdx.x * 64;

    float acc[4][4];
    #pragma unroll
    for (int i = 0; i < 4; i++)
        #pragma unroll
        for (int j = 0; j < 4; j++) acc[i][j] = 0.f;

    for (int k0 = 0; k0 < K; k0 += 16) {
        // A: 64 rows x 16 k -> 256 float4 loads
        {
            int r  = tid >> 2;           // 0..63
            int kq = (tid & 3) * 4;      // 0,4,8,12
            int gr = rowBase + r;
            float4 v = make_float4(0.f, 0.f, 0.f, 0.f);
            if (gr < M) v = *(const float4*)(A + (size_t)gr * K + k0 + kq);
            As[kq + 0][r] = v.x; As[kq + 1][r] = v.y;
            As[kq + 2][r] = v.z; As[kq + 3][r] = v.w;
        }
        // B: 16 k x 64 cols -> 256 float4 loads
        {
            int kr = tid >> 4;           // 0..15
            int c  = (tid & 15) * 4;     // 0..60
            float4 v = *(const float4*)(B + (size_t)(k0 + kr) * Ncols + colBase + c);
            Bs[kr][c + 0] = v.x; Bs[kr][c + 1] = v.y;
            Bs[kr][c + 2] = v.z; Bs[kr][c + 3] = v.w;
        }
        __syncthreads();
        #pragma unroll
        for (int kk = 0; kk < 16; kk++) {
            float a[4], b[4];
            #pragma unroll
            for (int i = 0; i < 4; i++) a[i] = As[kk][ty * 4 + i];
            #pragma unroll
            for (int j = 0; j < 4; j++) b[j] = Bs[kk][tx * 4 + j];
            #pragma unroll
            for (int i = 0; i < 4; i++)
                #pragma unroll
                for (int j = 0; j < 4; j++) acc[i][j] = fmaf(a[i], b[j], acc[i][j]);
        }
        __syncthreads();
    }

    #pragma unroll
    for (int i = 0; i < 4; i++) {
        int gr = rowBase + ty * 4 + i;
        if (gr < M) {
            float4 v = make_float4(acc[i][0], acc[i][1], acc[i][2], acc[i][3]);
            *(float4*)(C + (size_t)gr * Ncols + colBase + tx * 4) = v;
        }
    }
}

// ---------------------------------------------------------------------------
// alpha_s / alpha_d: one warp per (node, head), 64-dim dot products
// ---------------------------------------------------------------------------
__global__ void k_alpha(int selH, const float* __restrict__ a, int heads, int n_units)
{
    const float* h = buf_ptr(selH);
    int unit = blockIdx.x * (blockDim.x >> 5) + (threadIdx.x >> 5);
    if (unit >= n_units) return;
    int lane = threadIdx.x & 31;
    int node = unit / heads;
    int hd   = unit - node * heads;

    const float* hrow = h + (size_t)node * heads * 64 + hd * 64;
    float x0 = hrow[lane], x1 = hrow[lane + 32];
    const float* arow = a + hd * 128;
    float s = x0 * arow[lane]      + x1 * arow[lane + 32];
    float d = x0 * arow[64 + lane] + x1 * arow[96 + lane];
    #pragma unroll
    for (int o = 16; o > 0; o >>= 1) {
        s += __shfl_xor_sync(0xffffffffu, s, o);
        d += __shfl_xor_sync(0xffffffffu, d, o);
    }
    if (lane == 0) { g_alphaS[unit] = s; g_alphaD[unit] = d; }
}

// ---------------------------------------------------------------------------
// Aggregation: one warp per (node, head), online softmax over in-edges.
// out = sum_j softmax(leaky_relu(aS[src_j]+aD[dst]))_j * h[src_j]
// ---------------------------------------------------------------------------
template<int HEADS_T, bool ELU_T>
__global__ void k_agg(int selH, float* __restrict__ outExt, int selOut)
{
    const float* h = buf_ptr(selH);
    float* out = outExt ? outExt : buf_ptr(selOut);
    const int stride = HEADS_T * 64;

    int unit = blockIdx.x * (blockDim.x >> 5) + (threadIdx.x >> 5);
    if (unit >= NN * HEADS_T) return;
    int lane = threadIdx.x & 31;
    int n  = unit / HEADS_T;
    int hd = unit - n * HEADS_T;

    int beg = g_rowptr[n], end = g_rowptr[n + 1];
    float ad = g_alphaD[unit];

    float m = -INFINITY, s = 0.f, acc0 = 0.f, acc1 = 0.f;
    for (int i = beg; i < end; i++) {
        int   src = __ldg(&g_csr_src[i]);
        float e   = __ldg(&g_alphaS[src * HEADS_T + hd]) + ad;
        e = (e > 0.f) ? e : 0.2f * e;               // leaky_relu
        float newm = fmaxf(m, e);
        float corr = __expf(m - newm);              // 0 on first iter (m=-inf)
        float p    = __expf(e - newm);
        m = newm;
        s = s * corr + p;
        const float* hrow = h + (size_t)src * stride + hd * 64;
        acc0 = acc0 * corr + p * __ldg(&hrow[lane]);
        acc1 = acc1 * corr + p * __ldg(&hrow[lane + 32]);
    }

    float inv = 1.f / (s + 1e-16f);
    float o0 = acc0 * inv, o1 = acc1 * inv;
    if (beg == end) { o0 = 0.f; o1 = 0.f; }
    if (ELU_T) {
        o0 = (o0 > 0.f) ? o0 : expm1f(o0);
        o1 = (o1 > 0.f) ? o1 : expm1f(o1);
    }
    out[(size_t)n * stride + hd * 64 + lane]      = o0;
    out[(size_t)n * stride + hd * 64 + lane + 32] = o1;
}

// ---------------------------------------------------------------------------
// Launch
// ---------------------------------------------------------------------------
extern "C" void kernel_launch(void* const* d_in, const int* in_sizes, int n_in,
                              void* d_out, int out_size)
{
    const float* x  = (const float*)d_in[0];
    const int*   ei = (const int*)  d_in[1];
    const float* W0 = (const float*)d_in[2];
    const float* a0 = (const float*)d_in[3];
    const float* W1 = (const float*)d_in[4];
    const float* a1 = (const float*)d_in[5];
    const float* W2 = (const float*)d_in[6];
    const float* a2 = (const float*)d_in[7];
    float* out = (float*)d_out;

    const int zb  = (NN + 255) / 256;
    const int eb  = (EE + 255) / 256;
    const int sb  = (NN + 1023) / 1024;       // 98 scan blocks
    const dim3 g256(4, (NN + 63) / 64);       // GEMM grid, Ncols=256
    const dim3 g64 (1, (NN + 63) / 64);       // GEMM grid, Ncols=64

    // ---- CSR by dst ----
    k_zero_fill<<<zb, 256>>>();
    k_hist<<<eb, 256>>>(ei);
    k_scan1<<<sb, 1024>>>();
    k_scan2<<<1, 32>>>(sb);
    k_scan3<<<sb, 1024>>>();
    k_zero_fill<<<zb, 256>>>();
    k_scatter<<<eb, 256>>>(ei);

    const int aggWarpsBlk = 8;   // 256 threads
    int units4 = NN * NHEADS;
    int aggBlk4 = (units4 + aggWarpsBlk - 1) / aggWarpsBlk;
    int units1 = NN;
    int aggBlk1 = (units1 + aggWarpsBlk - 1) / aggWarpsBlk;
    int alphaBlk4 = (units4 + 7) / 8;
    int alphaBlk1 = (units1 + 7) / 8;

    // ---- layer 0: x(ext) @ W0 -> bufA ; agg -> bufB (+ELU) ----
    k_gemm64<<<g256, 256>>>(x, 0, /*C=*/0, W0, NN, 256, INDIM);
    k_alpha<<<alphaBlk4, 256>>>(/*h=*/0, a0, NHEADS, units4);
    k_agg<NHEADS, true><<<aggBlk4, 256>>>(/*h=*/0, nullptr, /*out=*/1);

    // ---- layer 1: bufB @ W1 -> bufA ; agg -> bufB (+ELU) ----
    k_gemm64<<<g256, 256>>>(nullptr, /*A=*/1, /*C=*/0, W1, NN, 256, 256);
    k_alpha<<<alphaBlk4, 256>>>(0, a1, NHEADS, units4);
    k_agg<NHEADS, true><<<aggBlk4, 256>>>(0, nullptr, 1);

    // ---- layer 2: bufB @ W2 -> bufA ; agg -> d_out (no ELU, 1 head) ----
    k_gemm64<<<g64, 256>>>(nullptr, 1, 0, W2, NN, 64, 256);
    k_alpha<<<alphaBlk1, 256>>>(0, a2, 1, units1);
    k_agg<1, false><<<aggBlk1, 256>>>(0, out, 0);
}

// round 3
// speedup vs baseline: 1.3418x; 1.3418x over previous
#include <cuda_runtime.h>
#include <math.h>

// Problem constants
#define NN      100000
#define EE      1600000
#define INDIM   128
#define HIDD    64
#define NHEADS  4
#define ODIM    64

// ---------------------------------------------------------------------------
// Scratch (device globals — the sanctioned no-alloc path)
// ---------------------------------------------------------------------------
__device__ float g_bufA[(size_t)NN * 256];   // GEMM outputs (h)
__device__ float g_bufB[(size_t)NN * 256];   // aggregated/ELU outputs
__device__ float g_alphaS[NN * NHEADS];
__device__ float g_alphaD[NN * NHEADS];
__device__ int   g_rowptr[NN + 1];
__device__ int   g_fill[NN];
__device__ int   g_csr_src[EE];
__device__ int   g_bsums[128];

__device__ __forceinline__ float* buf_ptr(int sel) {
    return sel == 0 ? g_bufA : g_bufB;
}

// ---------------------------------------------------------------------------
// CSR build: histogram -> exclusive scan -> scatter
// ---------------------------------------------------------------------------
__global__ void k_zero_fill() {
    int i = blockIdx.x * blockDim.x + threadIdx.x;
    if (i < NN) g_fill[i] = 0;
}

__global__ void k_hist(const int* __restrict__ ei) {
    int e = blockIdx.x * blockDim.x + threadIdx.x;
    if (e < EE) atomicAdd(&g_fill[ei[EE + e]], 1);
}

__global__ void k_scan1() {
    __shared__ int s[1024];
    int t = threadIdx.x;
    int i = blockIdx.x * 1024 + t;
    int v = (i < NN) ? g_fill[i] : 0;
    s[t] = v;
    __syncthreads();
    #pragma unroll
    for (int off = 1; off < 1024; off <<= 1) {
        int add = (t >= off) ? s[t - off] : 0;
        __syncthreads();
        s[t] += add;
        __syncthreads();
    }
    if (i < NN) g_rowptr[i] = s[t] - v;   // exclusive
    if (t == 1023) g_bsums[blockIdx.x] = s[1023];
}

__global__ void k_scan2(int nb) {
    if (threadIdx.x == 0 && blockIdx.x == 0) {
        int run = 0;
        for (int b = 0; b < nb; b++) { int v = g_bsums[b]; g_bsums[b] = run; run += v; }
        g_rowptr[NN] = run;   // == EE
    }
}

__global__ void k_scan3() {
    int i = blockIdx.x * 1024 + threadIdx.x;
    if (i < NN) g_rowptr[i] += g_bsums[blockIdx.x];
}

__global__ void k_scatter(const int* __restrict__ ei) {
    int e = blockIdx.x * blockDim.x + threadIdx.x;
    if (e < EE) {
        int d   = ei[EE + e];
        int pos = g_rowptr[d] + atomicAdd(&g_fill[d], 1);
        g_csr_src[pos] = ei[e];
    }
}

// ---------------------------------------------------------------------------
// TF32 tensor-core GEMM: C[M x Ncols] = A[M x K] * B[K x Ncols], row-major.
// BM=128, BN=64, BK=16. 256 threads = 8 warps (4 along M x 2 along N),
// each warp computes 32x32 via 2x4 m16n8k8 fragments.
// Smem strides chosen so fragment LDS is bank-conflict-free:
//   As[m][k]: stride 20  -> bank = (lane>>2)*20 + (lane&3)  mod 32, all distinct
//   Bs[k][n]: stride 72  -> bank = (lane&3)*8  + (lane>>2)  mod 32, all distinct
// ---------------------------------------------------------------------------
__device__ __forceinline__ unsigned f2tf(float x) {
    unsigned r;
    asm("cvt.rna.tf32.f32 %0, %1;" : "=r"(r) : "f"(x));
    return r;
}

__device__ __forceinline__ void mma_tf32(float* c, const unsigned* a, const unsigned* b) {
    asm volatile(
        "mma.sync.aligned.m16n8k8.row.col.f32.tf32.tf32.f32 "
        "{%0,%1,%2,%3}, {%4,%5,%6,%7}, {%8,%9}, {%0,%1,%2,%3};\n"
        : "+f"(c[0]), "+f"(c[1]), "+f"(c[2]), "+f"(c[3])
        : "r"(a[0]), "r"(a[1]), "r"(a[2]), "r"(a[3]), "r"(b[0]), "r"(b[1]));
}

__global__ void __launch_bounds__(256)
k_gemm_tf32(const float* __restrict__ Aext, int selA, int selC,
            const float* __restrict__ B, int M, int Ncols, int K)
{
    const float* A = Aext ? Aext : buf_ptr(selA);
    float* C = buf_ptr(selC);

    __shared__ unsigned As[128][20];   // [m][k], pad 16->20
    __shared__ unsigned Bs[16][72];    // [k][n], pad 64->72

    int tid  = threadIdx.x;
    int lane = tid & 31;
    int wid  = tid >> 5;
    int warp_m = wid & 3;     // 0..3, 32 rows each
    int warp_n = wid >> 2;    // 0..1, 32 cols each
    int rowBase = blockIdx.y * 128;
    int colBase = blockIdx.x * 64;

    float acc[2][4][4];
    #pragma unroll
    for (int mt = 0; mt < 2; mt++)
        #pragma unroll
        for (int nt = 0; nt < 4; nt++)
            #pragma unroll
            for (int i = 0; i < 4; i++) acc[mt][nt][i] = 0.f;

    for (int k0 = 0; k0 < K; k0 += 16) {
        // A: 128 rows x 16 k. 256 threads x 2 float4.
        #pragma unroll
        for (int i = 0; i < 2; i++) {
            int r  = (tid >> 2) + i * 64;
            int kq = (tid & 3) * 4;
            int gr = rowBase + r;
            float4 v = make_float4(0.f, 0.f, 0.f, 0.f);
            if (gr < M) v = *(const float4*)(A + (size_t)gr * K + k0 + kq);
            As[r][kq + 0] = f2tf(v.x); As[r][kq + 1] = f2tf(v.y);
            As[r][kq + 2] = f2tf(v.z); As[r][kq + 3] = f2tf(v.w);
        }
        // B: 16 k x 64 cols. 256 threads x 1 float4.
        {
            int kr = tid >> 4;
            int c  = (tid & 15) * 4;
            float4 v = *(const float4*)(B + (size_t)(k0 + kr) * Ncols + colBase + c);
            Bs[kr][c + 0] = f2tf(v.x); Bs[kr][c + 1] = f2tf(v.y);
            Bs[kr][c + 2] = f2tf(v.z); Bs[kr][c + 3] = f2tf(v.w);
        }
        __syncthreads();

        #pragma unroll
        for (int kk = 0; kk < 16; kk += 8) {
            unsigned af[2][4], bf[4][2];
            #pragma unroll
            for (int mt = 0; mt < 2; mt++) {
                int r0 = warp_m * 32 + mt * 16 + (lane >> 2);
                int kc = kk + (lane & 3);
                af[mt][0] = As[r0][kc];
                af[mt][1] = As[r0 + 8][kc];
                af[mt][2] = As[r0][kc + 4];
                af[mt][3] = As[r0 + 8][kc + 4];
            }
            #pragma unroll
            for (int nt = 0; nt < 4; nt++) {
                int cn = warp_n * 32 + nt * 8 + (lane >> 2);
                bf[nt][0] = Bs[kk + (lane & 3)][cn];
                bf[nt][1] = Bs[kk + (lane & 3) + 4][cn];
            }
            #pragma unroll
            for (int mt = 0; mt < 2; mt++)
                #pragma unroll
                for (int nt = 0; nt < 4; nt++)
                    mma_tf32(acc[mt][nt], af[mt], bf[nt]);
        }
        __syncthreads();
    }

    // Epilogue: each thread owns 2 rows x 2 cols per fragment.
    #pragma unroll
    for (int mt = 0; mt < 2; mt++) {
        int r0 = rowBase + warp_m * 32 + mt * 16 + (lane >> 2);
        #pragma unroll
        for (int nt = 0; nt < 4; nt++) {
            int c0 = colBase + warp_n * 32 + nt * 8 + (lane & 3) * 2;
            if (r0 < M) {
                float2 v = make_float2(acc[mt][nt][0], acc[mt][nt][1]);
                *(float2*)(C + (size_t)r0 * Ncols + c0) = v;
            }
            if (r0 + 8 < M) {
                float2 v = make_float2(acc[mt][nt][2], acc[mt][nt][3]);
                *(float2*)(C + (size_t)(r0 + 8) * Ncols + c0) = v;
            }
        }
    }
}

// ---------------------------------------------------------------------------
// alpha_s / alpha_d: one warp per (node, head), 64-dim dot products
// ---------------------------------------------------------------------------
__global__ void k_alpha(int selH, const float* __restrict__ a, int heads, int n_units)
{
    const float* h = buf_ptr(selH);
    int unit = blockIdx.x * (blockDim.x >> 5) + (threadIdx.x >> 5);
    if (unit >= n_units) return;
    int lane = threadIdx.x & 31;
    int node = unit / heads;
    int hd   = unit - node * heads;

    const float* hrow = h + (size_t)node * heads * 64 + hd * 64;
    float x0 = hrow[lane], x1 = hrow[lane + 32];
    const float* arow = a + hd * 128;
    float s = x0 * arow[lane]      + x1 * arow[lane + 32];
    float d = x0 * arow[64 + lane] + x1 * arow[96 + lane];
    #pragma unroll
    for (int o = 16; o > 0; o >>= 1) {
        s += __shfl_xor_sync(0xffffffffu, s, o);
        d += __shfl_xor_sync(0xffffffffu, d, o);
    }
    if (lane == 0) { g_alphaS[unit] = s; g_alphaD[unit] = d; }
}

// ---------------------------------------------------------------------------
// Aggregation: one warp per (node, head), online softmax over in-edges.
// ---------------------------------------------------------------------------
template<int HEADS_T, bool ELU_T>
__global__ void k_agg(int selH, float* __restrict__ outExt, int selOut)
{
    const float* h = buf_ptr(selH);
    float* out = outExt ? outExt : buf_ptr(selOut);
    const int stride = HEADS_T * 64;

    int unit = blockIdx.x * (blockDim.x >> 5) + (threadIdx.x >> 5);
    if (unit >= NN * HEADS_T) return;
    int lane = threadIdx.x & 31;
    int n  = unit / HEADS_T;
    int hd = unit - n * HEADS_T;

    int beg = g_rowptr[n], end = g_rowptr[n + 1];
    float ad = g_alphaD[unit];

    float m = -INFINITY, s = 0.f, acc0 = 0.f, acc1 = 0.f;
    for (int i = beg; i < end; i++) {
        int   src = __ldg(&g_csr_src[i]);
        float e   = __ldg(&g_alphaS[src * HEADS_T + hd]) + ad;
        e = (e > 0.f) ? e : 0.2f * e;               // leaky_relu
        float newm = fmaxf(m, e);
        float corr = __expf(m - newm);              // 0 on first iter (m=-inf)
        float p    = __expf(e - newm);
        m = newm;
        s = s * corr + p;
        const float* hrow = h + (size_t)src * stride + hd * 64;
        acc0 = acc0 * corr + p * __ldg(&hrow[lane]);
        acc1 = acc1 * corr + p * __ldg(&hrow[lane + 32]);
    }

    float inv = 1.f / (s + 1e-16f);
    float o0 = acc0 * inv, o1 = acc1 * inv;
    if (beg == end) { o0 = 0.f; o1 = 0.f; }
    if (ELU_T) {
        o0 = (o0 > 0.f) ? o0 : expm1f(o0);
        o1 = (o1 > 0.f) ? o1 : expm1f(o1);
    }
    out[(size_t)n * stride + hd * 64 + lane]      = o0;
    out[(size_t)n * stride + hd * 64 + lane + 32] = o1;
}

// ---------------------------------------------------------------------------
// Launch
// ---------------------------------------------------------------------------
extern "C" void kernel_launch(void* const* d_in, const int* in_sizes, int n_in,
                              void* d_out, int out_size)
{
    const float* x  = (const float*)d_in[0];
    const int*   ei = (const int*)  d_in[1];
    const float* W0 = (const float*)d_in[2];
    const float* a0 = (const float*)d_in[3];
    const float* W1 = (const float*)d_in[4];
    const float* a1 = (const float*)d_in[5];
    const float* W2 = (const float*)d_in[6];
    const float* a2 = (const float*)d_in[7];
    float* out = (float*)d_out;

    const int zb  = (NN + 255) / 256;
    const int eb  = (EE + 255) / 256;
    const int sb  = (NN + 1023) / 1024;
    const dim3 g256(4, (NN + 127) / 128);     // GEMM grid, Ncols=256
    const dim3 g64 (1, (NN + 127) / 128);     // GEMM grid, Ncols=64

    // ---- CSR by dst ----
    k_zero_fill<<<zb, 256>>>();
    k_hist<<<eb, 256>>>(ei);
    k_scan1<<<sb, 1024>>>();
    k_scan2<<<1, 32>>>(sb);
    k_scan3<<<sb, 1024>>>();
    k_zero_fill<<<zb, 256>>>();
    k_scatter<<<eb, 256>>>(ei);

    const int aggWarpsBlk = 8;   // 256 threads
    int units4 = NN * NHEADS;
    int aggBlk4 = (units4 + aggWarpsBlk - 1) / aggWarpsBlk;
    int units1 = NN;
    int aggBlk1 = (units1 + aggWarpsBlk - 1) / aggWarpsBlk;
    int alphaBlk4 = (units4 + 7) / 8;
    int alphaBlk1 = (units1 + 7) / 8;

    // ---- layer 0: x(ext) @ W0 -> bufA ; agg -> bufB (+ELU) ----
    k_gemm_tf32<<<g256, 256>>>(x, 0, /*C=*/0, W0, NN, 256, INDIM);
    k_alpha<<<alphaBlk4, 256>>>(/*h=*/0, a0, NHEADS, units4);
    k_agg<NHEADS, true><<<aggBlk4, 256>>>(/*h=*/0, nullptr, /*out=*/1);

    // ---- layer 1: bufB @ W1 -> bufA ; agg -> bufB (+ELU) ----
    k_gemm_tf32<<<g256, 256>>>(nullptr, /*A=*/1, /*C=*/0, W1, NN, 256, 256);
    k_alpha<<<alphaBlk4, 256>>>(0, a1, NHEADS, units4);
    k_agg<NHEADS, true><<<aggBlk4, 256>>>(0, nullptr, 1);

    // ---- layer 2: bufB @ W2 -> bufA ; agg -> d_out (no ELU, 1 head) ----
    k_gemm_tf32<<<g64, 256>>>(nullptr, 1, 0, W2, NN, 64, 256);
    k_alpha<<<alphaBlk1, 256>>>(0, a2, 1, units1);
    k_agg<1, false><<<aggBlk1, 256>>>(0, out, 0);
}

// round 4
// speedup vs baseline: 1.3964x; 1.0406x over previous
#include <cuda_runtime.h>
#include <math.h>

// Problem constants
#define NN      100000
#define EE      1600000
#define INDIM   128
#define HIDD    64
#define NHEADS  4
#define ODIM    64

// ---------------------------------------------------------------------------
// Scratch (device globals — the sanctioned no-alloc path)
// ---------------------------------------------------------------------------
__device__ float g_bufA[(size_t)NN * 256];   // GEMM outputs (h)
__device__ float g_bufB[(size_t)NN * 256];   // aggregated/ELU outputs
__device__ float g_alphaS[NN * NHEADS];
__device__ float g_alphaD[NN * NHEADS];
__device__ int   g_rowptr[NN + 1];
__device__ int   g_fill[NN];
__device__ int   g_csr_src[EE];
__device__ int   g_bsums[128];

__device__ __forceinline__ float* buf_ptr(int sel) {
    return sel == 0 ? g_bufA : g_bufB;
}

// ---------------------------------------------------------------------------
// CSR build: histogram -> exclusive scan -> scatter
// ---------------------------------------------------------------------------
__global__ void k_zero_fill() {
    int i = blockIdx.x * blockDim.x + threadIdx.x;
    if (i < NN) g_fill[i] = 0;
}

__global__ void k_hist(const int* __restrict__ ei) {
    int e = blockIdx.x * blockDim.x + threadIdx.x;
    if (e < EE) atomicAdd(&g_fill[ei[EE + e]], 1);
}

__global__ void k_scan1() {
    __shared__ int s[1024];
    int t = threadIdx.x;
    int i = blockIdx.x * 1024 + t;
    int v = (i < NN) ? g_fill[i] : 0;
    s[t] = v;
    __syncthreads();
    #pragma unroll
    for (int off = 1; off < 1024; off <<= 1) {
        int add = (t >= off) ? s[t - off] : 0;
        __syncthreads();
        s[t] += add;
        __syncthreads();
    }
    if (i < NN) g_rowptr[i] = s[t] - v;   // exclusive
    if (t == 1023) g_bsums[blockIdx.x] = s[1023];
}

__global__ void k_scan2(int nb) {
    if (threadIdx.x == 0 && blockIdx.x == 0) {
        int run = 0;
        for (int b = 0; b < nb; b++) { int v = g_bsums[b]; g_bsums[b] = run; run += v; }
        g_rowptr[NN] = run;   // == EE
    }
}

__global__ void k_scan3() {
    int i = blockIdx.x * 1024 + threadIdx.x;
    if (i < NN) g_rowptr[i] += g_bsums[blockIdx.x];
}

__global__ void k_scatter(const int* __restrict__ ei) {
    int e = blockIdx.x * blockDim.x + threadIdx.x;
    if (e < EE) {
        int d   = ei[EE + e];
        int pos = g_rowptr[d] + atomicAdd(&g_fill[d], 1);
        g_csr_src[pos] = ei[e];
    }
}

// ---------------------------------------------------------------------------
// TF32 tensor-core GEMM with cp.async double buffering.
// C[M x Ncols] = A[M x K] * B[K x Ncols], row-major.
// BM=128, BN=64, BK=16, 2 stages. 256 threads = 8 warps (4 M x 2 N),
// each warp computes 32x32 via 2x4 m16n8k8 fragments.
// Smem rows padded so fragment LDS is bank-conflict-free AND 16B-aligned:
//   As stride 20 floats (80B), Bs stride 72 floats (288B).
// Conversion f32->tf32 (cvt.rna) happens at fragment load -> numerics
// identical to the single-stage version (same accumulation order).
// ---------------------------------------------------------------------------
__device__ __forceinline__ unsigned f2tf(float x) {
    unsigned r;
    asm("cvt.rna.tf32.f32 %0, %1;" : "=r"(r) : "f"(x));
    return r;
}

__device__ __forceinline__ void mma_tf32(float* c, const unsigned* a, const unsigned* b) {
    asm volatile(
        "mma.sync.aligned.m16n8k8.row.col.f32.tf32.tf32.f32 "
        "{%0,%1,%2,%3}, {%4,%5,%6,%7}, {%8,%9}, {%0,%1,%2,%3};\n"
        : "+f"(c[0]), "+f"(c[1]), "+f"(c[2]), "+f"(c[3])
        : "r"(a[0]), "r"(a[1]), "r"(a[2]), "r"(a[3]), "r"(b[0]), "r"(b[1]));
}

__device__ __forceinline__ void cp16(void* smem, const void* gmem, bool pred) {
    unsigned saddr = (unsigned)__cvta_generic_to_shared(smem);
    int sz = pred ? 16 : 0;   // src-size 0 => zero-fill, no global access
    asm volatile("cp.async.cg.shared.global [%0], [%1], 16, %2;\n"
                 :: "r"(saddr), "l"(gmem), "r"(sz));
}

__global__ void __launch_bounds__(256)
k_gemm_tf32(const float* __restrict__ Aext, int selA, int selC,
            const float* __restrict__ B, int M, int Ncols, int K)
{
    const float* A = Aext ? Aext : buf_ptr(selA);
    float* C = buf_ptr(selC);

    __shared__ float As[2][128][20];   // [stage][m][k]
    __shared__ float Bs[2][16][72];    // [stage][k][n]

    int tid  = threadIdx.x;
    int lane = tid & 31;
    int wid  = tid >> 5;
    int warp_m = wid & 3;     // 0..3, 32 rows each
    int warp_n = wid >> 2;    // 0..1, 32 cols each
    int rowBase = blockIdx.y * 128;
    int colBase = blockIdx.x * 64;

    // per-thread async-load coords
    int ar = tid >> 2;          // 0..63 (rows ar and ar+64)
    int ak = (tid & 3) * 4;     // 0,4,8,12
    int br = tid >> 4;          // 0..15
    int bc = (tid & 15) * 4;    // 0..60

    const float* aSrc0 = A + (size_t)(rowBase + ar) * K + ak;
    const float* aSrc1 = A + (size_t)(rowBase + ar + 64) * K + ak;
    const float* bSrc  = B + (size_t)br * Ncols + colBase + bc;
    bool aOk0 = (rowBase + ar)      < M;
    bool aOk1 = (rowBase + ar + 64) < M;

    float acc[2][4][4];
    #pragma unroll
    for (int mt = 0; mt < 2; mt++)
        #pragma unroll
        for (int nt = 0; nt < 4; nt++)
            #pragma unroll
            for (int i = 0; i < 4; i++) acc[mt][nt][i] = 0.f;

    int nIter = K >> 4;

    // prologue: stage 0
    cp16(&As[0][ar][ak],      aSrc0, aOk0);
    cp16(&As[0][ar + 64][ak], aSrc1, aOk1);
    cp16(&Bs[0][br][bc],      bSrc,  true);
    asm volatile("cp.async.commit_group;\n" ::: "memory");

    for (int it = 0; it < nIter; it++) {
        int s = it & 1;
        if (it + 1 < nIter) {
            int k0n = (it + 1) << 4;
            cp16(&As[s ^ 1][ar][ak],      aSrc0 + k0n, aOk0);
            cp16(&As[s ^ 1][ar + 64][ak], aSrc1 + k0n, aOk1);
            cp16(&Bs[s ^ 1][br][bc],      bSrc + (size_t)k0n * Ncols, true);
            asm volatile("cp.async.commit_group;\n" ::: "memory");
            asm volatile("cp.async.wait_group 1;\n" ::: "memory");
        } else {
            asm volatile("cp.async.wait_group 0;\n" ::: "memory");
        }
        __syncthreads();

        #pragma unroll
        for (int kk = 0; kk < 16; kk += 8) {
            unsigned af[2][4], bf[4][2];
            #pragma unroll
            for (int mt = 0; mt < 2; mt++) {
                int r0 = warp_m * 32 + mt * 16 + (lane >> 2);
                int kc = kk + (lane & 3);
                af[mt][0] = f2tf(As[s][r0][kc]);
                af[mt][1] = f2tf(As[s][r0 + 8][kc]);
                af[mt][2] = f2tf(As[s][r0][kc + 4]);
                af[mt][3] = f2tf(As[s][r0 + 8][kc + 4]);
            }
            #pragma unroll
            for (int nt = 0; nt < 4; nt++) {
                int cn = warp_n * 32 + nt * 8 + (lane >> 2);
                bf[nt][0] = f2tf(Bs[s][kk + (lane & 3)][cn]);
                bf[nt][1] = f2tf(Bs[s][kk + (lane & 3) + 4][cn]);
            }
            #pragma unroll
            for (int mt = 0; mt < 2; mt++)
                #pragma unroll
                for (int nt = 0; nt < 4; nt++)
                    mma_tf32(acc[mt][nt], af[mt], bf[nt]);
        }
        __syncthreads();
    }

    // Epilogue: each thread owns 2 rows x 2 cols per fragment.
    #pragma unroll
    for (int mt = 0; mt < 2; mt++) {
        int r0 = rowBase + warp_m * 32 + mt * 16 + (lane >> 2);
        #pragma unroll
        for (int nt = 0; nt < 4; nt++) {
            int c0 = colBase + warp_n * 32 + nt * 8 + (lane & 3) * 2;
            if (r0 < M) {
                float2 v = make_float2(acc[mt][nt][0], acc[mt][nt][1]);
                *(float2*)(C + (size_t)r0 * Ncols + c0) = v;
            }
            if (r0 + 8 < M) {
                float2 v = make_float2(acc[mt][nt][2], acc[mt][nt][3]);
                *(float2*)(C + (size_t)(r0 + 8) * Ncols + c0) = v;
            }
        }
    }
}

// ---------------------------------------------------------------------------
// alpha_s / alpha_d: one warp per (node, head), 64-dim dot products
// ---------------------------------------------------------------------------
__global__ void k_alpha(int selH, const float* __restrict__ a, int heads, int n_units)
{
    const float* h = buf_ptr(selH);
    int unit = blockIdx.x * (blockDim.x >> 5) + (threadIdx.x >> 5);
    if (unit >= n_units) return;
    int lane = threadIdx.x & 31;
    int node = unit / heads;
    int hd   = unit - node * heads;

    const float* hrow = h + (size_t)node * heads * 64 + hd * 64;
    float x0 = hrow[lane], x1 = hrow[lane + 32];
    const float* arow = a + hd * 128;
    float s = x0 * arow[lane]      + x1 * arow[lane + 32];
    float d = x0 * arow[64 + lane] + x1 * arow[96 + lane];
    #pragma unroll
    for (int o = 16; o > 0; o >>= 1) {
        s += __shfl_xor_sync(0xffffffffu, s, o);
        d += __shfl_xor_sync(0xffffffffu, d, o);
    }
    if (lane == 0) { g_alphaS[unit] = s; g_alphaD[unit] = d; }
}

// ---------------------------------------------------------------------------
// Aggregation: one warp per (node, head), online softmax over in-edges.
// ---------------------------------------------------------------------------
template<int HEADS_T, bool ELU_T>
__global__ void k_agg(int selH, float* __restrict__ outExt, int selOut)
{
    const float* h = buf_ptr(selH);
    float* out = outExt ? outExt : buf_ptr(selOut);
    const int stride = HEADS_T * 64;

    int unit = blockIdx.x * (blockDim.x >> 5) + (threadIdx.x >> 5);
    if (unit >= NN * HEADS_T) return;
    int lane = threadIdx.x & 31;
    int n  = unit / HEADS_T;
    int hd = unit - n * HEADS_T;

    int beg = g_rowptr[n], end = g_rowptr[n + 1];
    float ad = g_alphaD[unit];

    float m = -INFINITY, s = 0.f, acc0 = 0.f, acc1 = 0.f;
    for (int i = beg; i < end; i++) {
        int   src = __ldg(&g_csr_src[i]);
        float e   = __ldg(&g_alphaS[src * HEADS_T + hd]) + ad;
        e = (e > 0.f) ? e : 0.2f * e;               // leaky_relu
        float newm = fmaxf(m, e);
        float corr = __expf(m - newm);              // 0 on first iter (m=-inf)
        float p    = __expf(e - newm);
        m = newm;
        s = s * corr + p;
        const float* hrow = h + (size_t)src * stride + hd * 64;
        acc0 = acc0 * corr + p * __ldg(&hrow[lane]);
        acc1 = acc1 * corr + p * __ldg(&hrow[lane + 32]);
    }

    float inv = 1.f / (s + 1e-16f);
    float o0 = acc0 * inv, o1 = acc1 * inv;
    if (beg == end) { o0 = 0.f; o1 = 0.f; }
    if (ELU_T) {
        o0 = (o0 > 0.f) ? o0 : expm1f(o0);
        o1 = (o1 > 0.f) ? o1 : expm1f(o1);
    }
    out[(size_t)n * stride + hd * 64 + lane]      = o0;
    out[(size_t)n * stride + hd * 64 + lane + 32] = o1;
}

// ---------------------------------------------------------------------------
// Launch
// ---------------------------------------------------------------------------
extern "C" void kernel_launch(void* const* d_in, const int* in_sizes, int n_in,
                              void* d_out, int out_size)
{
    const float* x  = (const float*)d_in[0];
    const int*   ei = (const int*)  d_in[1];
    const float* W0 = (const float*)d_in[2];
    const float* a0 = (const float*)d_in[3];
    const float* W1 = (const float*)d_in[4];
    const float* a1 = (const float*)d_in[5];
    const float* W2 = (const float*)d_in[6];
    const float* a2 = (const float*)d_in[7];
    float* out = (float*)d_out;

    const int zb  = (NN + 255) / 256;
    const int eb  = (EE + 255) / 256;
    const int sb  = (NN + 1023) / 1024;
    const dim3 g256(4, (NN + 127) / 128);     // GEMM grid, Ncols=256
    const dim3 g64 (1, (NN + 127) / 128);     // GEMM grid, Ncols=64

    // ---- CSR by dst ----
    k_zero_fill<<<zb, 256>>>();
    k_hist<<<eb, 256>>>(ei);
    k_scan1<<<sb, 1024>>>();
    k_scan2<<<1, 32>>>(sb);
    k_scan3<<<sb, 1024>>>();
    k_zero_fill<<<zb, 256>>>();
    k_scatter<<<eb, 256>>>(ei);

    const int aggWarpsBlk = 8;   // 256 threads
    int units4 = NN * NHEADS;
    int aggBlk4 = (units4 + aggWarpsBlk - 1) / aggWarpsBlk;
    int units1 = NN;
    int aggBlk1 = (units1 + aggWarpsBlk - 1) / aggWarpsBlk;
    int alphaBlk4 = (units4 + 7) / 8;
    int alphaBlk1 = (units1 + 7) / 8;

    // ---- layer 0: x(ext) @ W0 -> bufA ; agg -> bufB (+ELU) ----
    k_gemm_tf32<<<g256, 256>>>(x, 0, /*C=*/0, W0, NN, 256, INDIM);
    k_alpha<<<alphaBlk4, 256>>>(/*h=*/0, a0, NHEADS, units4);
    k_agg<NHEADS, true><<<aggBlk4, 256>>>(/*h=*/0, nullptr, /*out=*/1);

    // ---- layer 1: bufB @ W1 -> bufA ; agg -> bufB (+ELU) ----
    k_gemm_tf32<<<g256, 256>>>(nullptr, /*A=*/1, /*C=*/0, W1, NN, 256, 256);
    k_alpha<<<alphaBlk4, 256>>>(0, a1, NHEADS, units4);
    k_agg<NHEADS, true><<<aggBlk4, 256>>>(0, nullptr, 1);

    // ---- layer 2: bufB @ W2 -> bufA ; agg -> d_out (no ELU, 1 head) ----
    k_gemm_tf32<<<g64, 256>>>(nullptr, 1, 0, W2, NN, 64, 256);
    k_alpha<<<alphaBlk1, 256>>>(0, a2, 1, units1);
    k_agg<1, false><<<aggBlk1, 256>>>(0, out, 0);
}

// round 5
// speedup vs baseline: 1.4529x; 1.0405x over previous
#include <cuda_runtime.h>
#include <math.h>

// Problem constants
#define NN      100000
#define EE      1600000
#define INDIM   128
#define HIDD    64
#define NHEADS  4
#define ODIM    64

// ---------------------------------------------------------------------------
// Scratch (device globals — the sanctioned no-alloc path)
// ---------------------------------------------------------------------------
__device__ float g_bufA[(size_t)NN * 256];   // GEMM outputs (h)
__device__ float g_bufB[(size_t)NN * 256];   // agg outputs / rounded x
__device__ float g_wr[128*256 + 256*256 + 256*64];   // tf32-rounded weights
__device__ float g_alphaS[NN * NHEADS];
__device__ float g_alphaD[NN * NHEADS];
__device__ int   g_rowptr[NN + 1];
__device__ int   g_fill[NN];
__device__ int   g_csr_src[EE];
__device__ int   g_bsums[128];

__device__ __forceinline__ float* buf_ptr(int sel) {
    return sel == 0 ? g_bufA : g_bufB;
}

__device__ __forceinline__ unsigned f2tf(float x) {
    unsigned r;
    asm("cvt.rna.tf32.f32 %0, %1;" : "=r"(r) : "f"(x));
    return r;
}

// ---------------------------------------------------------------------------
// tf32 pre-rounding pass (idempotent: values are re-truncated at MMA anyway)
// dstSel: 0=bufA, 1=bufB, 2=g_wr
// ---------------------------------------------------------------------------
__global__ void k_round(const float* __restrict__ src, int dstSel, int dstOff, int n)
{
    float* dst = (dstSel == 2 ? g_wr : buf_ptr(dstSel)) + dstOff;
    int i = blockIdx.x * blockDim.x + threadIdx.x;
    int stride = gridDim.x * blockDim.x;
    for (; i < n; i += stride)
        dst[i] = __uint_as_float(f2tf(src[i]));
}

// ---------------------------------------------------------------------------
// CSR build: histogram -> exclusive scan -> scatter
// ---------------------------------------------------------------------------
__global__ void k_zero_fill() {
    int i = blockIdx.x * blockDim.x + threadIdx.x;
    if (i < NN) g_fill[i] = 0;
}

__global__ void k_hist(const int* __restrict__ ei) {
    int e = blockIdx.x * blockDim.x + threadIdx.x;
    if (e < EE) atomicAdd(&g_fill[ei[EE + e]], 1);
}

__global__ void k_scan1() {
    __shared__ int s[1024];
    int t = threadIdx.x;
    int i = blockIdx.x * 1024 + t;
    int v = (i < NN) ? g_fill[i] : 0;
    s[t] = v;
    __syncthreads();
    #pragma unroll
    for (int off = 1; off < 1024; off <<= 1) {
        int add = (t >= off) ? s[t - off] : 0;
        __syncthreads();
        s[t] += add;
        __syncthreads();
    }
    if (i < NN) g_rowptr[i] = s[t] - v;   // exclusive
    if (t == 1023) g_bsums[blockIdx.x] = s[1023];
}

__global__ void k_scan2(int nb) {
    if (threadIdx.x == 0 && blockIdx.x == 0) {
        int run = 0;
        for (int b = 0; b < nb; b++) { int v = g_bsums[b]; g_bsums[b] = run; run += v; }
        g_rowptr[NN] = run;   // == EE
    }
}

__global__ void k_scan3() {
    int i = blockIdx.x * 1024 + threadIdx.x;
    if (i < NN) g_rowptr[i] += g_bsums[blockIdx.x];
}

__global__ void k_scatter(const int* __restrict__ ei) {
    int e = blockIdx.x * blockDim.x + threadIdx.x;
    if (e < EE) {
        int d   = ei[EE + e];
        int pos = g_rowptr[d] + atomicAdd(&g_fill[d], 1);
        g_csr_src[pos] = ei[e];
    }
}

// ---------------------------------------------------------------------------
// TF32 tensor-core GEMM + fused alpha epilogue.
// C[M x Ncols] = A[M x K] * B[K x Ncols]; A,B already tf32-rounded.
// BM=128, BN=64, BK=16, 2-stage cp.async. 256 threads = 8 warps (4 M x 2 N).
// Each block covers exactly one head's 64 columns -> alpha_s/alpha_d for its
// 128 rows are computed in-register and stored (no separate alpha kernel).
// ---------------------------------------------------------------------------
__device__ __forceinline__ void mma_tf32(float* c, const unsigned* a, const unsigned* b) {
    asm volatile(
        "mma.sync.aligned.m16n8k8.row.col.f32.tf32.tf32.f32 "
        "{%0,%1,%2,%3}, {%4,%5,%6,%7}, {%8,%9}, {%0,%1,%2,%3};\n"
        : "+f"(c[0]), "+f"(c[1]), "+f"(c[2]), "+f"(c[3])
        : "r"(a[0]), "r"(a[1]), "r"(a[2]), "r"(a[3]), "r"(b[0]), "r"(b[1]));
}

__device__ __forceinline__ void cp16(void* smem, const void* gmem, bool pred) {
    unsigned saddr = (unsigned)__cvta_generic_to_shared(smem);
    int sz = pred ? 16 : 0;   // src-size 0 => zero-fill, no global access
    asm volatile("cp.async.cg.shared.global [%0], [%1], 16, %2;\n"
                 :: "r"(saddr), "l"(gmem), "r"(sz));
}

__global__ void __launch_bounds__(256)
k_gemm_tf32(int selA, int selC, int wOff,
            const float* __restrict__ aVec, int heads,
            int M, int Ncols, int K)
{
    const float* A = buf_ptr(selA);
    const float* B = g_wr + wOff;
    float* C = buf_ptr(selC);

    __shared__ float As[2][128][20];   // [stage][m][k]
    __shared__ float Bs[2][16][72];    // [stage][k][n]
    __shared__ float a_sh[128];        // a_s (0..63) | a_d (64..127) for this head
    __shared__ float sAl[128], dAl[128];

    int tid  = threadIdx.x;
    int lane = tid & 31;
    int wid  = tid >> 5;
    int warp_m = wid & 3;     // 0..3, 32 rows each
    int warp_n = wid >> 2;    // 0..1, 32 cols each
    int rowBase = blockIdx.y * 128;
    int colBase = blockIdx.x * 64;
    int head    = blockIdx.x;          // Ncols=64 => grid.x=1 => head 0

    if (tid < 128) {
        a_sh[tid] = aVec[head * 128 + tid];
        sAl[tid] = 0.f;
        dAl[tid] = 0.f;
    }

    // per-thread async-load coords
    int ar = tid >> 2;          // 0..63 (rows ar and ar+64)
    int ak = (tid & 3) * 4;     // 0,4,8,12
    int br = tid >> 4;          // 0..15
    int bc = (tid & 15) * 4;    // 0..60

    const float* aSrc0 = A + (size_t)(rowBase + ar) * K + ak;
    const float* aSrc1 = A + (size_t)(rowBase + ar + 64) * K + ak;
    const float* bSrc  = B + (size_t)br * Ncols + colBase + bc;
    bool aOk0 = (rowBase + ar)      < M;
    bool aOk1 = (rowBase + ar + 64) < M;

    float acc[2][4][4];
    #pragma unroll
    for (int mt = 0; mt < 2; mt++)
        #pragma unroll
        for (int nt = 0; nt < 4; nt++)
            #pragma unroll
            for (int i = 0; i < 4; i++) acc[mt][nt][i] = 0.f;

    int nIter = K >> 4;

    // prologue: stage 0
    cp16(&As[0][ar][ak],      aSrc0, aOk0);
    cp16(&As[0][ar + 64][ak], aSrc1, aOk1);
    cp16(&Bs[0][br][bc],      bSrc,  true);
    asm volatile("cp.async.commit_group;\n" ::: "memory");

    for (int it = 0; it < nIter; it++) {
        int s = it & 1;
        if (it + 1 < nIter) {
            int k0n = (it + 1) << 4;
            cp16(&As[s ^ 1][ar][ak],      aSrc0 + k0n, aOk0);
            cp16(&As[s ^ 1][ar + 64][ak], aSrc1 + k0n, aOk1);
            cp16(&Bs[s ^ 1][br][bc],      bSrc + (size_t)k0n * Ncols, true);
            asm volatile("cp.async.commit_group;\n" ::: "memory");
            asm volatile("cp.async.wait_group 1;\n" ::: "memory");
        } else {
            asm volatile("cp.async.wait_group 0;\n" ::: "memory");
        }
        __syncthreads();

        #pragma unroll
        for (int kk = 0; kk < 16; kk += 8) {
            unsigned af[2][4], bf[4][2];
            #pragma unroll
            for (int mt = 0; mt < 2; mt++) {
                int r0 = warp_m * 32 + mt * 16 + (lane >> 2);
                int kc = kk + (lane & 3);
                af[mt][0] = __float_as_uint(As[s][r0][kc]);
                af[mt][1] = __float_as_uint(As[s][r0 + 8][kc]);
                af[mt][2] = __float_as_uint(As[s][r0][kc + 4]);
                af[mt][3] = __float_as_uint(As[s][r0 + 8][kc + 4]);
            }
            #pragma unroll
            for (int nt = 0; nt < 4; nt++) {
                int cn = warp_n * 32 + nt * 8 + (lane >> 2);
                bf[nt][0] = __float_as_uint(Bs[s][kk + (lane & 3)][cn]);
                bf[nt][1] = __float_as_uint(Bs[s][kk + (lane & 3) + 4][cn]);
            }
            #pragma unroll
            for (int mt = 0; mt < 2; mt++)
                #pragma unroll
                for (int nt = 0; nt < 4; nt++)
                    mma_tf32(acc[mt][nt], af[mt], bf[nt]);
        }
        __syncthreads();
    }

    // ---- Epilogue: store C (raw f32) + fused alpha ----
    float s_part[2][2] = {{0.f,0.f},{0.f,0.f}};
    float d_part[2][2] = {{0.f,0.f},{0.f,0.f}};

    #pragma unroll
    for (int mt = 0; mt < 2; mt++) {
        int r0 = rowBase + warp_m * 32 + mt * 16 + (lane >> 2);
        #pragma unroll
        for (int nt = 0; nt < 4; nt++) {
            int cn = warp_n * 32 + nt * 8 + (lane & 3) * 2;   // block-local col
            int c0 = colBase + cn;
            if (r0 < M) {
                float2 v = make_float2(acc[mt][nt][0], acc[mt][nt][1]);
                *(float2*)(C + (size_t)r0 * Ncols + c0) = v;
            }
            if (r0 + 8 < M) {
                float2 v = make_float2(acc[mt][nt][2], acc[mt][nt][3]);
                *(float2*)(C + (size_t)(r0 + 8) * Ncols + c0) = v;
            }
            float as0 = a_sh[cn], as1 = a_sh[cn + 1];
            float ad0 = a_sh[64 + cn], ad1 = a_sh[64 + cn + 1];
            s_part[mt][0] += acc[mt][nt][0] * as0 + acc[mt][nt][1] * as1;
            d_part[mt][0] += acc[mt][nt][0] * ad0 + acc[mt][nt][1] * ad1;
            s_part[mt][1] += acc[mt][nt][2] * as0 + acc[mt][nt][3] * as1;
            d_part[mt][1] += acc[mt][nt][2] * ad0 + acc[mt][nt][3] * ad1;
        }
    }
    // reduce across the 4 lanes holding the same row (lane&3 = 0..3)
    #pragma unroll
    for (int mt = 0; mt < 2; mt++)
        #pragma unroll
        for (int sl = 0; sl < 2; sl++) {
            #pragma unroll
            for (int o = 1; o < 4; o <<= 1) {
                s_part[mt][sl] += __shfl_xor_sync(0xffffffffu, s_part[mt][sl], o);
                d_part[mt][sl] += __shfl_xor_sync(0xffffffffu, d_part[mt][sl], o);
            }
        }
    if ((lane & 3) == 0) {
        #pragma unroll
        for (int mt = 0; mt < 2; mt++) {
            int rloc = warp_m * 32 + mt * 16 + (lane >> 2);
            atomicAdd(&sAl[rloc],     s_part[mt][0]);
            atomicAdd(&dAl[rloc],     d_part[mt][0]);
            atomicAdd(&sAl[rloc + 8], s_part[mt][1]);
            atomicAdd(&dAl[rloc + 8], d_part[mt][1]);
        }
    }
    __syncthreads();
    if (tid < 128) {
        int r = rowBase + tid;
        if (r < M) {
            g_alphaS[r * heads + head] = sAl[tid];
            g_alphaD[r * heads + head] = dAl[tid];
        }
    }
}

// ---------------------------------------------------------------------------
// Aggregation: one warp per (node, head), online softmax over in-edges.
// ROUND_T: write output pre-rounded to tf32 (feeds next GEMM; idempotent).
// ---------------------------------------------------------------------------
template<int HEADS_T, bool ELU_T, bool ROUND_T>
__global__ void k_agg(int selH, float* __restrict__ outExt, int selOut)
{
    const float* h = buf_ptr(selH);
    float* out = outExt ? outExt : buf_ptr(selOut);
    const int stride = HEADS_T * 64;

    int unit = blockIdx.x * (blockDim.x >> 5) + (threadIdx.x >> 5);
    if (unit >= NN * HEADS_T) return;
    int lane = threadIdx.x & 31;
    int n  = unit / HEADS_T;
    int hd = unit - n * HEADS_T;

    int beg = g_rowptr[n], end = g_rowptr[n + 1];
    float ad = g_alphaD[unit];

    float m = -INFINITY, s = 0.f, acc0 = 0.f, acc1 = 0.f;
    for (int i = beg; i < end; i++) {
        int   src = __ldg(&g_csr_src[i]);
        float e   = __ldg(&g_alphaS[src * HEADS_T + hd]) + ad;
        e = (e > 0.f) ? e : 0.2f * e;               // leaky_relu
        float newm = fmaxf(m, e);
        float corr = __expf(m - newm);              // 0 on first iter (m=-inf)
        float p    = __expf(e - newm);
        m = newm;
        s = s * corr + p;
        const float* hrow = h + (size_t)src * stride + hd * 64;
        acc0 = acc0 * corr + p * __ldg(&hrow[lane]);
        acc1 = acc1 * corr + p * __ldg(&hrow[lane + 32]);
    }

    float inv = 1.f / (s + 1e-16f);
    float o0 = acc0 * inv, o1 = acc1 * inv;
    if (beg == end) { o0 = 0.f; o1 = 0.f; }
    if (ELU_T) {
        o0 = (o0 > 0.f) ? o0 : expm1f(o0);
        o1 = (o1 > 0.f) ? o1 : expm1f(o1);
    }
    if (ROUND_T) {
        o0 = __uint_as_float(f2tf(o0));
        o1 = __uint_as_float(f2tf(o1));
    }
    out[(size_t)n * stride + hd * 64 + lane]      = o0;
    out[(size_t)n * stride + hd * 64 + lane + 32] = o1;
}

// ---------------------------------------------------------------------------
// Launch
// ---------------------------------------------------------------------------
extern "C" void kernel_launch(void* const* d_in, const int* in_sizes, int n_in,
                              void* d_out, int out_size)
{
    const float* x  = (const float*)d_in[0];
    const int*   ei = (const int*)  d_in[1];
    const float* W0 = (const float*)d_in[2];
    const float* a0 = (const float*)d_in[3];
    const float* W1 = (const float*)d_in[4];
    const float* a1 = (const float*)d_in[5];
    const float* W2 = (const float*)d_in[6];
    const float* a2 = (const float*)d_in[7];
    float* out = (float*)d_out;

    const int zb  = (NN + 255) / 256;
    const int eb  = (EE + 255) / 256;
    const int sb  = (NN + 1023) / 1024;
    const dim3 g256(4, (NN + 127) / 128);     // GEMM grid, Ncols=256
    const dim3 g64 (1, (NN + 127) / 128);     // GEMM grid, Ncols=64

    const int W0_OFF = 0;
    const int W1_OFF = 128 * 256;
    const int W2_OFF = 128 * 256 + 256 * 256;

    // ---- tf32 pre-rounding: x -> bufB, weights -> g_wr ----
    k_round<<<1184, 256>>>(x,  1, 0, NN * INDIM);
    k_round<<<128,  256>>>(W0, 2, W0_OFF, 128 * 256);
    k_round<<<256,  256>>>(W1, 2, W1_OFF, 256 * 256);
    k_round<<<64,   256>>>(W2, 2, W2_OFF, 256 * 64);

    // ---- CSR by dst ----
    k_zero_fill<<<zb, 256>>>();
    k_hist<<<eb, 256>>>(ei);
    k_scan1<<<sb, 1024>>>();
    k_scan2<<<1, 32>>>(sb);
    k_scan3<<<sb, 1024>>>();
    k_zero_fill<<<zb, 256>>>();
    k_scatter<<<eb, 256>>>(ei);

    const int aggWarpsBlk = 8;   // 256 threads
    int units4 = NN * NHEADS;
    int aggBlk4 = (units4 + aggWarpsBlk - 1) / aggWarpsBlk;
    int units1 = NN;
    int aggBlk1 = (units1 + aggWarpsBlk - 1) / aggWarpsBlk;

    // ---- layer 0: bufB(x~) @ W0 -> bufA (+alpha) ; agg -> bufB (+ELU, tf32) ----
    k_gemm_tf32<<<g256, 256>>>(/*A=*/1, /*C=*/0, W0_OFF, a0, NHEADS, NN, 256, INDIM);
    k_agg<NHEADS, true, true><<<aggBlk4, 256>>>(/*h=*/0, nullptr, /*out=*/1);

    // ---- layer 1: bufB @ W1 -> bufA (+alpha) ; agg -> bufB (+ELU, tf32) ----
    k_gemm_tf32<<<g256, 256>>>(1, 0, W1_OFF, a1, NHEADS, NN, 256, 256);
    k_agg<NHEADS, true, true><<<aggBlk4, 256>>>(0, nullptr, 1);

    // ---- layer 2: bufB @ W2 -> bufA (+alpha) ; agg -> d_out (no ELU, no round) ----
    k_gemm_tf32<<<g64, 256>>>(1, 0, W2_OFF, a2, 1, NN, 64, 256);
    k_agg<1, false, false><<<aggBlk1, 256>>>(0, out, 0);
}